// round 1
// baseline (speedup 1.0000x reference)
#include <cuda_runtime.h>
#include <math.h>

// Problem constants
constexpr int PB = 2;      // batch
constexpr int PT = 2048;   // query seq
constexpr int PS = 2048;   // key/value seq
constexpr int PD = 1024;   // model dim
constexpr int PH = 16;     // heads
constexpr int PDK = 64;    // head dim

// ---------------------------------------------------------------------------
// Scratch (device globals — no allocation allowed)
// ---------------------------------------------------------------------------
__device__ float g_q[(size_t)PB * PH * PT * PDK];   // (B,H,T,DK)
__device__ float g_k[(size_t)PB * PH * PS * PDK];   // (B,H,S,DK)
__device__ float g_v[(size_t)PB * PH * PS * PDK];   // (B,H,S,DK)
__device__ float g_attn[(size_t)PB * PT * PD];      // (B,T,H*DK)

constexpr int BM = 128, BN = 128, BK = 16;

// Projection GEMM: C = A(MxK)*W(KxN)+bias, stored as ((b*H+h)*SEQ+t)*DK+dk
__global__ __launch_bounds__(256) void proj_gemm_kernel(
    const float* __restrict__ A, const float* __restrict__ W,
    const float* __restrict__ bias, float* __restrict__ Cout,
    int M, int N, int K)
{
    __shared__ float As[BK][BM + 4];
    __shared__ float Bs[BK][BN];

    const int tid = threadIdx.x;
    const int tx = tid & 15;
    const int ty = tid >> 4;
    const int bm = blockIdx.y * BM;
    const int bn = blockIdx.x * BN;

    const int aCol = (tid & 3) * 4;
    const int aRow = tid >> 2;
    const int bCol = (tid & 31) * 4;
    const int bRow = tid >> 5;

    float acc[8][8];
#pragma unroll
    for (int i = 0; i < 8; i++)
#pragma unroll
        for (int j = 0; j < 8; j++) acc[i][j] = 0.f;

    for (int k0 = 0; k0 < K; k0 += BK) {
#pragma unroll
        for (int p = 0; p < 2; p++) {
            int r = aRow + p * 64;
            float4 av = *(const float4*)(A + (size_t)(bm + r) * K + k0 + aCol);
            As[aCol + 0][r] = av.x;
            As[aCol + 1][r] = av.y;
            As[aCol + 2][r] = av.z;
            As[aCol + 3][r] = av.w;
        }
#pragma unroll
        for (int p = 0; p < 2; p++) {
            int r = bRow + p * 8;
            *(float4*)&Bs[r][bCol] =
                *(const float4*)(W + (size_t)(k0 + r) * N + bn + bCol);
        }
        __syncthreads();

#pragma unroll
        for (int kk = 0; kk < BK; kk++) {
            float ra[8], rb[8];
            *(float4*)&ra[0] = *(float4*)&As[kk][ty * 8];
            *(float4*)&ra[4] = *(float4*)&As[kk][ty * 8 + 4];
            *(float4*)&rb[0] = *(float4*)&Bs[kk][tx * 8];
            *(float4*)&rb[4] = *(float4*)&Bs[kk][tx * 8 + 4];
#pragma unroll
            for (int i = 0; i < 8; i++)
#pragma unroll
                for (int j = 0; j < 8; j++)
                    acc[i][j] += ra[i] * rb[j];
        }
        __syncthreads();
    }

    const int col0 = bn + tx * 8;
    const int h = col0 / PDK;
    const int dk = col0 - h * PDK;   // 8 cols stay within one head (8 | 64)
#pragma unroll
    for (int i = 0; i < 8; i++) {
        int row = bm + ty * 8 + i;
        int b = row / PT;
        int t = row - b * PT;
        size_t base = (((size_t)(b * PH + h) * PT) + t) * PDK + dk;
#pragma unroll
        for (int j = 0; j < 8; j++)
            Cout[base + j] = acc[i][j] + bias[col0 + j];
    }
}

// Plain GEMM: C[row*N+col] = A*W + bias
__global__ __launch_bounds__(256) void plain_gemm_kernel(
    const float* __restrict__ A, const float* __restrict__ W,
    const float* __restrict__ bias, float* __restrict__ C,
    int M, int N, int K)
{
    __shared__ float As[BK][BM + 4];
    __shared__ float Bs[BK][BN];

    const int tid = threadIdx.x;
    const int tx = tid & 15;
    const int ty = tid >> 4;
    const int bm = blockIdx.y * BM;
    const int bn = blockIdx.x * BN;

    const int aCol = (tid & 3) * 4;
    const int aRow = tid >> 2;
    const int bCol = (tid & 31) * 4;
    const int bRow = tid >> 5;

    float acc[8][8];
#pragma unroll
    for (int i = 0; i < 8; i++)
#pragma unroll
        for (int j = 0; j < 8; j++) acc[i][j] = 0.f;

    for (int k0 = 0; k0 < K; k0 += BK) {
#pragma unroll
        for (int p = 0; p < 2; p++) {
            int r = aRow + p * 64;
            float4 av = *(const float4*)(A + (size_t)(bm + r) * K + k0 + aCol);
            As[aCol + 0][r] = av.x;
            As[aCol + 1][r] = av.y;
            As[aCol + 2][r] = av.z;
            As[aCol + 3][r] = av.w;
        }
#pragma unroll
        for (int p = 0; p < 2; p++) {
            int r = bRow + p * 8;
            *(float4*)&Bs[r][bCol] =
                *(const float4*)(W + (size_t)(k0 + r) * N + bn + bCol);
        }
        __syncthreads();

#pragma unroll
        for (int kk = 0; kk < BK; kk++) {
            float ra[8], rb[8];
            *(float4*)&ra[0] = *(float4*)&As[kk][ty * 8];
            *(float4*)&ra[4] = *(float4*)&As[kk][ty * 8 + 4];
            *(float4*)&rb[0] = *(float4*)&Bs[kk][tx * 8];
            *(float4*)&rb[4] = *(float4*)&Bs[kk][tx * 8 + 4];
#pragma unroll
            for (int i = 0; i < 8; i++)
#pragma unroll
                for (int j = 0; j < 8; j++)
                    acc[i][j] += ra[i] * rb[j];
        }
        __syncthreads();
    }

    const int col0 = bn + tx * 8;
#pragma unroll
    for (int i = 0; i < 8; i++) {
        int row = bm + ty * 8 + i;
        float* dst = C + (size_t)row * N + col0;
#pragma unroll
        for (int j = 0; j < 8; j++) dst[j] = acc[i][j] + bias[col0 + j];
    }
}

// ---------------------------------------------------------------------------
// Flash attention (fp32, online softmax)
// ---------------------------------------------------------------------------
constexpr int ABR = 64, ABC = 64, APAD = 68;
constexpr int ATTN_SMEM = 3 * 64 * APAD * 4;

__global__ __launch_bounds__(128) void attn_kernel(
    const float* __restrict__ q, const float* __restrict__ k,
    const float* __restrict__ v, float* __restrict__ o)
{
    extern __shared__ float sm[];
    float* Qs = sm;                  // [64][APAD]
    float* Ks = sm + 64 * APAD;      // [64][APAD], reused as P tile
    float* Vt = sm + 2 * 64 * APAD;  // [64(d)][APAD] transposed V

    const int tid = threadIdx.x;
    const int rg = tid >> 3;   // rows rg*4 .. rg*4+3
    const int cg = tid & 7;    // cols cg + 8*j
    const int t0 = blockIdx.x * ABR;
    const int h = blockIdx.y;
    const int b = blockIdx.z;

    const float* qb = q + (((size_t)(b * PH + h) * PT) + t0) * PDK;
    const float* kb = k + (size_t)(b * PH + h) * PS * PDK;
    const float* vb = v + (size_t)(b * PH + h) * PS * PDK;

    for (int idx = tid; idx < 64 * 16; idx += 128) {
        int r = idx >> 4;
        int c4 = (idx & 15) << 2;
        float4 qv = *(const float4*)(qb + r * PDK + c4);
        Qs[r * APAD + c4 + 0] = qv.x * 0.125f;
        Qs[r * APAD + c4 + 1] = qv.y * 0.125f;
        Qs[r * APAD + c4 + 2] = qv.z * 0.125f;
        Qs[r * APAD + c4 + 3] = qv.w * 0.125f;
    }

    float m[4], l[4], O[4][8];
#pragma unroll
    for (int i = 0; i < 4; i++) {
        m[i] = -1e30f;
        l[i] = 0.f;
#pragma unroll
        for (int j = 0; j < 8; j++) O[i][j] = 0.f;
    }

    for (int s0 = 0; s0 < PS; s0 += ABC) {
        for (int idx = tid; idx < 64 * 16; idx += 128) {
            int r = idx >> 4;
            int c4 = (idx & 15) << 2;
            *(float4*)&Ks[r * APAD + c4] =
                *(const float4*)(kb + (size_t)(s0 + r) * PDK + c4);
            float4 vv = *(const float4*)(vb + (size_t)(s0 + r) * PDK + c4);
            Vt[(c4 + 0) * APAD + r] = vv.x;
            Vt[(c4 + 1) * APAD + r] = vv.y;
            Vt[(c4 + 2) * APAD + r] = vv.z;
            Vt[(c4 + 3) * APAD + r] = vv.w;
        }
        __syncthreads();

        float sc[4][8];
#pragma unroll
        for (int i = 0; i < 4; i++)
#pragma unroll
            for (int j = 0; j < 8; j++) sc[i][j] = 0.f;

#pragma unroll
        for (int kk = 0; kk < 64; kk += 4) {
            float4 qv[4], kv[8];
#pragma unroll
            for (int i = 0; i < 4; i++)
                qv[i] = *(float4*)&Qs[(rg * 4 + i) * APAD + kk];
#pragma unroll
            for (int j = 0; j < 8; j++)
                kv[j] = *(float4*)&Ks[(cg + 8 * j) * APAD + kk];
#pragma unroll
            for (int i = 0; i < 4; i++)
#pragma unroll
                for (int j = 0; j < 8; j++) {
                    sc[i][j] += qv[i].x * kv[j].x;
                    sc[i][j] += qv[i].y * kv[j].y;
                    sc[i][j] += qv[i].z * kv[j].z;
                    sc[i][j] += qv[i].w * kv[j].w;
                }
        }
        __syncthreads();

        float* Ps = Ks;
#pragma unroll
        for (int i = 0; i < 4; i++) {
            float mx = sc[i][0];
#pragma unroll
            for (int j = 1; j < 8; j++) mx = fmaxf(mx, sc[i][j]);
            mx = fmaxf(mx, __shfl_xor_sync(0xFFFFFFFFu, mx, 1));
            mx = fmaxf(mx, __shfl_xor_sync(0xFFFFFFFFu, mx, 2));
            mx = fmaxf(mx, __shfl_xor_sync(0xFFFFFFFFu, mx, 4));
            float mn = fmaxf(m[i], mx);
            float corr = __expf(m[i] - mn);
            float rs = 0.f;
#pragma unroll
            for (int j = 0; j < 8; j++) {
                float p = __expf(sc[i][j] - mn);
                sc[i][j] = p;
                rs += p;
            }
            rs += __shfl_xor_sync(0xFFFFFFFFu, rs, 1);
            rs += __shfl_xor_sync(0xFFFFFFFFu, rs, 2);
            rs += __shfl_xor_sync(0xFFFFFFFFu, rs, 4);
            l[i] = l[i] * corr + rs;
            m[i] = mn;
#pragma unroll
            for (int j = 0; j < 8; j++) O[i][j] *= corr;
#pragma unroll
            for (int j = 0; j < 8; j++)
                Ps[(rg * 4 + i) * APAD + cg + 8 * j] = sc[i][j];
        }
        __syncthreads();

#pragma unroll
        for (int ss = 0; ss < 64; ss += 4) {
            float4 pv[4], vv[8];
#pragma unroll
            for (int i = 0; i < 4; i++)
                pv[i] = *(float4*)&Ps[(rg * 4 + i) * APAD + ss];
#pragma unroll
            for (int j = 0; j < 8; j++)
                vv[j] = *(float4*)&Vt[(cg + 8 * j) * APAD + ss];
#pragma unroll
            for (int i = 0; i < 4; i++)
#pragma unroll
                for (int j = 0; j < 8; j++) {
                    O[i][j] += pv[i].x * vv[j].x;
                    O[i][j] += pv[i].y * vv[j].y;
                    O[i][j] += pv[i].z * vv[j].z;
                    O[i][j] += pv[i].w * vv[j].w;
                }
        }
        __syncthreads();
    }

#pragma unroll
    for (int i = 0; i < 4; i++) {
        float inv = 1.0f / l[i];
        int t = t0 + rg * 4 + i;
        size_t base = ((size_t)(b * PT + t)) * PD + h * PDK;
#pragma unroll
        for (int j = 0; j < 8; j++)
            o[base + cg + 8 * j] = O[i][j] * inv;
    }
}

// ---------------------------------------------------------------------------
extern "C" void kernel_launch(void* const* d_in, const int* in_sizes, int n_in,
                              void* d_out, int out_size)
{
    const float* query = (const float*)d_in[0];
    const float* value = (const float*)d_in[1];
    const float* key   = (const float*)d_in[2];
    const float* Wq    = (const float*)d_in[3];
    const float* bq    = (const float*)d_in[4];
    const float* Wk    = (const float*)d_in[5];
    const float* bk    = (const float*)d_in[6];
    const float* Wv    = (const float*)d_in[7];
    const float* bv    = (const float*)d_in[8];
    const float* Wo    = (const float*)d_in[9];
    const float* bo    = (const float*)d_in[10];
    float* out = (float*)d_out;

    float *gq, *gk, *gv, *ga;
    cudaGetSymbolAddress((void**)&gq, g_q);
    cudaGetSymbolAddress((void**)&gk, g_k);
    cudaGetSymbolAddress((void**)&gv, g_v);
    cudaGetSymbolAddress((void**)&ga, g_attn);

    const int M = PB * PT;   // 4096
    const int N = PD;        // 1024
    const int K = PD;        // 1024
    dim3 ggrid(N / BN, M / BM);  // (8, 32)

    proj_gemm_kernel<<<ggrid, 256>>>(query, Wq, bq, gq, M, N, K);
    proj_gemm_kernel<<<ggrid, 256>>>(key,   Wk, bk, gk, M, N, K);
    proj_gemm_kernel<<<ggrid, 256>>>(value, Wv, bv, gv, M, N, K);

    cudaFuncSetAttribute(attn_kernel,
                         cudaFuncAttributeMaxDynamicSharedMemorySize,
                         ATTN_SMEM);
    attn_kernel<<<dim3(PT / ABR, PH, PB), 128, ATTN_SMEM>>>(gq, gk, gv, ga);

    plain_gemm_kernel<<<ggrid, 256>>>(ga, Wo, bo, out, M, N, K);
}